// round 16
// baseline (speedup 1.0000x reference)
#include <cuda_runtime.h>
#include <cuda_fp16.h>
#include <cstdint>

// ---------------- problem constants ----------------
#define NIN   4096
#define NOUT  1024
#define BC    128          // B*C = 4*32
#define C_DIM 32

// GEMM: D[o(1024), bc(128)] = sum_k M[o,k] * gftT[bc,k]   (fp16 single-GEMM)
// CTA tile: 128 o x 64 bc; grid = 8 (o) x 2 (bc) x 16 (K-split) = 256 CTAs
#define KSPLIT 16
#define KPB    (NIN / KSPLIT)   // 256
#define KC     64               // k per smem chunk
#define NCHUNK (KPB / KC)       // 4
#define ROWH   72               // smem row stride in halves (144B = 9x16B)
#define ATILEH (128 * ROWH)     // A tile halves
#define BTILEH (64  * ROWH)     // B tile halves
#define STAGEH (ATILEH + BTILEH)   // halves per stage (A + single B)

// ---------------- device scratch ----------------
__device__ __align__(16) __half g_Mh[NOUT * NIN];  // 8.4 MB count matrix (fp16)
__device__ __align__(16) __half g_ghi[BC * NIN];   // 1 MB  (G@F)^T (fp16)

__device__ __forceinline__ uint32_t smem_u32(const void* p) {
    uint32_t a;
    asm("{ .reg .u64 t; cvta.to.shared.u64 t, %1; cvt.u32.u64 %0, t; }" : "=r"(a) : "l"(p));
    return a;
}
__device__ __forceinline__ void cp16(uint32_t dst, const void* src) {
    asm volatile("cp.async.cg.shared.global [%0], [%1], 16;" :: "r"(dst), "l"(src));
}
__device__ __forceinline__ void cp_commit() {
    asm volatile("cp.async.commit_group;" ::: "memory");
}
__device__ __forceinline__ void cp_wait0() {
    asm volatile("cp.async.wait_group 0;" ::: "memory");
}
__device__ __forceinline__ void ldsm_x4(uint32_t* r, uint32_t addr) {
    asm volatile("ldmatrix.sync.aligned.m8n8.x4.shared.b16 {%0,%1,%2,%3}, [%4];"
                 : "=r"(r[0]), "=r"(r[1]), "=r"(r[2]), "=r"(r[3]) : "r"(addr));
}
__device__ __forceinline__ void mma16816(float* c, const uint32_t* a,
                                         uint32_t b0, uint32_t b1) {
    asm volatile(
        "mma.sync.aligned.m16n8k16.row.col.f32.f16.f16.f32 "
        "{%0,%1,%2,%3}, {%4,%5,%6,%7}, {%8,%9}, {%0,%1,%2,%3};"
        : "+f"(c[0]), "+f"(c[1]), "+f"(c[2]), "+f"(c[3])
        : "r"(a[0]), "r"(a[1]), "r"(a[2]), "r"(a[3]), "r"(b0), "r"(b1));
}

// ---------------------------------------------------------------------------
// Kernel T: channel-GEMM -> gftT fp16. 512 blocks:
//   b = bid>>7, oc-half = (bid>>6)&1, n-tile = bid&63 (64 wide).
// Same inner loop as the measured-best variant; each thread does 4 oc x 1 n.
// ---------------------------------------------------------------------------
__global__ void qc_transform(const float* __restrict__ F,
                             const float* __restrict__ G) {
    __shared__ float Fs[C_DIM * 64];
    __shared__ float Gs[C_DIM * 33];
    int t    = threadIdx.x;
    int b    = blockIdx.x >> 7;            // 0..3
    int half = (blockIdx.x >> 6) & 1;      // oc half (0/1)
    int n0   = (blockIdx.x & 63) * 64;     // n tile start

    #pragma unroll
    for (int j = 0; j < 8; j++) {
        int idx = t + j * 256;                       // idx = i*64 + nl
        Fs[idx] = F[b * (C_DIM * NIN) + (idx >> 6) * NIN + n0 + (idx & 63)];
    }
    #pragma unroll
    for (int j = 0; j < 4; j++) {
        int idx = t + j * 256;
        Gs[(idx >> 5) * 33 + (idx & 31)] = G[idx];
    }
    __syncthreads();

    int nl  = t & 63;
    int ocg = t >> 6;                      // 0..3
    #pragma unroll
    for (int oo = 0; oo < 4; oo++) {
        int oc = half * 16 + ocg * 4 + oo;
        float s = 0.f;
        #pragma unroll
        for (int i = 0; i < 32; i++)
            s = fmaf(Gs[oc * 33 + i], Fs[i * 64 + nl], s);
        g_ghi[(b * 32 + oc) * NIN + n0 + nl] = __float2half_rn(s);
    }
}

// ---------------------------------------------------------------------------
// Kernel C: build count matrix. Thread per edge, spread fp16 atomics.
// ---------------------------------------------------------------------------
__global__ void qc_count(const int* __restrict__ idx_out,
                         const int* __restrict__ idx_in, int E) {
    int e = blockIdx.x * blockDim.x + threadIdx.x;
    if (e >= E) return;
    atomicAdd(&g_Mh[idx_out[e] * NIN + idx_in[e]], __float2half(1.0f));
}

// ---------------------------------------------------------------------------
// Kernel G: HMMA GEMM (single fp16 B), cp.async double-buffered.
// CTA = 256 threads (8 warps, 4 o-groups x 2 bc-groups), tile 128o x 64bc.
// Epilogue RED-adds into out (bc-major, zeroed by memset).
// ---------------------------------------------------------------------------
__global__ void __launch_bounds__(256, 2) qc_gemm_mma(float* __restrict__ out) {
    extern __shared__ __half sm[];
    int t    = threadIdx.x;
    int wid  = t >> 5;
    int lane = t & 31;
    int bid  = blockIdx.x;
    int mt_b = bid & 7;              // o tile
    int nb   = (bid >> 3) & 1;       // bc half
    int ks   = bid >> 4;             // K split
    int o0   = mt_b * 128;
    int bc0  = nb * 64;
    int k0   = ks * KPB;
    int wo   = (wid >> 1) * 32;      // warp o offset (0/32/64/96)
    int n0w  = (wid & 1) * 32;       // warp bc offset within CTA (0/32)

    uint32_t sbase = smem_u32(sm);
    uint32_t sA[2], sB[2];
    #pragma unroll
    for (int s = 0; s < 2; s++) {
        sA[s] = sbase + (s * STAGEH) * 2;
        sB[s] = sA[s] + ATILEH * 2;
    }

    auto prefetch = [&](int stage, int kc) {
        #pragma unroll
        for (int j = 0; j < 4; j++) {
            int seg = t + j * 256;                 // 0..1023
            int row = seg >> 3, col = seg & 7;
            cp16(sA[stage] + row * 144 + col * 16,
                 &g_Mh[(o0 + row) * NIN + kc + col * 8]);
        }
        #pragma unroll
        for (int j = 0; j < 2; j++) {
            int seg = t + j * 256;                 // 0..511
            int row = seg >> 3, col = seg & 7;
            cp16(sB[stage] + row * 144 + col * 16,
                 &g_ghi[(bc0 + row) * NIN + kc + col * 8]);
        }
        cp_commit();
    };

    prefetch(0, k0);

    float acc[2][4][4];
    #pragma unroll
    for (int i = 0; i < 2; i++)
        #pragma unroll
        for (int j = 0; j < 4; j++)
            #pragma unroll
            for (int q = 0; q < 4; q++) acc[i][j][q] = 0.f;

    for (int c = 0; c < NCHUNK; c++) {
        int buf = c & 1;
        cp_wait0();
        __syncthreads();

        if (c + 1 < NCHUNK) prefetch(buf ^ 1, k0 + (c + 1) * KC);

        #pragma unroll
        for (int kk = 0; kk < KC; kk += 16) {
            uint32_t a[2][4];
            #pragma unroll
            for (int mt = 0; mt < 2; mt++)
                ldsm_x4(a[mt], sA[buf] + 2 * ((wo + mt * 16 + (lane & 15)) * ROWH
                                              + kk + (lane >> 4) * 8));
            #pragma unroll
            for (int ng = 0; ng < 2; ng++) {
                uint32_t b[4];
                ldsm_x4(b, sB[buf] + 2 * ((n0w + ng * 16 + (lane & 15)) * ROWH
                                          + kk + (lane >> 4) * 8));
                #pragma unroll
                for (int mt = 0; mt < 2; mt++) {
                    mma16816(acc[mt][ng * 2 + 0], a[mt], b[0], b[2]);
                    mma16816(acc[mt][ng * 2 + 1], a[mt], b[1], b[3]);
                }
            }
        }
    }

    // Epilogue: RED into out[bc*NOUT + o]. Frag rows = lane>>2 (+8),
    // cols = (lane&3)*2 + {0,1}.
    #pragma unroll
    for (int mt = 0; mt < 2; mt++) {
        #pragma unroll
        for (int nt = 0; nt < 4; nt++) {
            int o  = o0 + wo + mt * 16 + (lane >> 2);
            int bc = bc0 + n0w + nt * 8 + (lane & 3) * 2;
            atomicAdd(&out[bc * NOUT + o],             acc[mt][nt][0]);
            atomicAdd(&out[(bc + 1) * NOUT + o],       acc[mt][nt][1]);
            atomicAdd(&out[bc * NOUT + o + 8],         acc[mt][nt][2]);
            atomicAdd(&out[(bc + 1) * NOUT + o + 8],   acc[mt][nt][3]);
        }
    }
}

// ---------------------------------------------------------------------------
extern "C" void kernel_launch(void* const* d_in, const int* in_sizes, int n_in,
                              void* d_out, int out_size) {
    const float* features = (const float*)d_in[0];   // (4,32,4096) f32
    const float* G        = (const float*)d_in[1];   // (32,32)     f32
    const int*   idx_out  = (const int*)d_in[2];     // (E,) i32
    const int*   idx_in   = (const int*)d_in[3];     // (E,) i32
    float*       out      = (float*)d_out;           // (4,32,1024) f32
    int E = in_sizes[2];

    static void* mh_ptr = nullptr;
    static bool inited = false;
    if (!inited) {
        cudaGetSymbolAddress(&mh_ptr, g_Mh);
        cudaFuncSetAttribute(qc_gemm_mma,
                             cudaFuncAttributeMaxDynamicSharedMemorySize,
                             2 * STAGEH * (int)sizeof(__half));
        inited = true;
    }
    const int GEMM_SMEM = 2 * STAGEH * (int)sizeof(__half);  // 55296

    // graph-capturable memset nodes: zero M (8.4 MB) and out (0.5 MB)
    cudaMemsetAsync(mh_ptr, 0, (size_t)NOUT * NIN * sizeof(__half), 0);
    cudaMemsetAsync(d_out, 0, (size_t)BC * NOUT * sizeof(float), 0);

    qc_transform<<<512, 256>>>(features, G);
    qc_count<<<(E + 255) / 256, 256>>>(idx_out, idx_in, E);
    qc_gemm_mma<<<8 * 2 * KSPLIT, 256, GEMM_SMEM>>>(out);
}

// round 17
// speedup vs baseline: 1.0518x; 1.0518x over previous
#include <cuda_runtime.h>
#include <cuda_fp16.h>
#include <cstdint>

// ---------------- problem constants ----------------
#define NIN   4096
#define NOUT  1024
#define BC    128          // B*C = 4*32
#define C_DIM 32

// GEMM: agg[o(1024), bc(128)] = sum_k M[o,k] * F[bc,k]   (fp16)
// CTA tile: 128 o x 64 bc; grid = 8 (o) x 2 (bc) x 16 (K-split) = 256 CTAs
#define KSPLIT 16
#define KPB    (NIN / KSPLIT)   // 256
#define KC     64               // k per smem chunk
#define NCHUNK (KPB / KC)       // 4
#define ROWH   72               // smem row stride in halves (144B = 9x16B)
#define ATILEH (128 * ROWH)     // A tile halves
#define BTILEH (64  * ROWH)     // B tile halves
#define STAGEH (ATILEH + BTILEH)   // halves per stage

// prep coverage: zero M (524288 uint4) + zero agg (32768 uint4)
//              + convert F (65536 uint4 outputs, 8 floats each)
#define ZV_M    524288
#define ZV_AGG  (ZV_M + 32768)         // 557056
#define PREP_ALL (ZV_AGG + 65536)      // 622592 -> 2432 blocks x 256

// ---------------- device scratch ----------------
__device__ __align__(16) __half g_Mh[NOUT * NIN];  // 8.4 MB count matrix (fp16)
__device__ __align__(16) __half g_Fh[BC * NIN];    // 1 MB  F in fp16 (same layout)
__device__ __align__(16) float  g_agg[BC * NOUT];  // 512 KB aggregated (pre-G)

__device__ __forceinline__ uint32_t smem_u32(const void* p) {
    uint32_t a;
    asm("{ .reg .u64 t; cvta.to.shared.u64 t, %1; cvt.u32.u64 %0, t; }" : "=r"(a) : "l"(p));
    return a;
}
__device__ __forceinline__ void cp16(uint32_t dst, const void* src) {
    asm volatile("cp.async.cg.shared.global [%0], [%1], 16;" :: "r"(dst), "l"(src));
}
__device__ __forceinline__ void cp_commit() {
    asm volatile("cp.async.commit_group;" ::: "memory");
}
__device__ __forceinline__ void cp_wait0() {
    asm volatile("cp.async.wait_group 0;" ::: "memory");
}
__device__ __forceinline__ void ldsm_x4(uint32_t* r, uint32_t addr) {
    asm volatile("ldmatrix.sync.aligned.m8n8.x4.shared.b16 {%0,%1,%2,%3}, [%4];"
                 : "=r"(r[0]), "=r"(r[1]), "=r"(r[2]), "=r"(r[3]) : "r"(addr));
}
__device__ __forceinline__ void mma16816(float* c, const uint32_t* a,
                                         uint32_t b0, uint32_t b1) {
    asm volatile(
        "mma.sync.aligned.m16n8k16.row.col.f32.f16.f16.f32 "
        "{%0,%1,%2,%3}, {%4,%5,%6,%7}, {%8,%9}, {%0,%1,%2,%3};"
        : "+f"(c[0]), "+f"(c[1]), "+f"(c[2]), "+f"(c[3])
        : "r"(a[0]), "r"(a[1]), "r"(a[2]), "r"(a[3]), "r"(b0), "r"(b1));
}

// ---------------------------------------------------------------------------
// Kernel P: zero M + zero agg + elementwise fp32->fp16 convert of F.
// F is (4,32,4096) = (128,4096) row-major == exactly the B layout the GEMM
// needs (bc rows, n cols). No transpose, no G here. 2432 uniform blocks.
// ---------------------------------------------------------------------------
__global__ void qc_prep(const float* __restrict__ F) {
    int gt = blockIdx.x * 256 + threadIdx.x;
    if (gt < ZV_M) {
        reinterpret_cast<uint4*>(g_Mh)[gt] = make_uint4(0u, 0u, 0u, 0u);
    } else if (gt < ZV_AGG) {
        reinterpret_cast<uint4*>(g_agg)[gt - ZV_M] = make_uint4(0u, 0u, 0u, 0u);
    } else {
        int i = gt - ZV_AGG;                       // 0..65535, 8 floats each
        const float4* f4 = reinterpret_cast<const float4*>(F);
        float4 a = f4[i * 2], b = f4[i * 2 + 1];
        __half2 h0 = __floats2half2_rn(a.x, a.y);
        __half2 h1 = __floats2half2_rn(a.z, a.w);
        __half2 h2 = __floats2half2_rn(b.x, b.y);
        __half2 h3 = __floats2half2_rn(b.z, b.w);
        uint4 o;
        o.x = *reinterpret_cast<uint32_t*>(&h0);
        o.y = *reinterpret_cast<uint32_t*>(&h1);
        o.z = *reinterpret_cast<uint32_t*>(&h2);
        o.w = *reinterpret_cast<uint32_t*>(&h3);
        reinterpret_cast<uint4*>(g_Fh)[i] = o;
    }
}

// ---------------------------------------------------------------------------
// Kernel C: build count matrix. Thread per edge, spread fp16 atomics.
// ---------------------------------------------------------------------------
__global__ void qc_count(const int* __restrict__ idx_out,
                         const int* __restrict__ idx_in, int E) {
    int e = blockIdx.x * blockDim.x + threadIdx.x;
    if (e >= E) return;
    atomicAdd(&g_Mh[idx_out[e] * NIN + idx_in[e]], __float2half(1.0f));
}

// ---------------------------------------------------------------------------
// Kernel G: HMMA GEMM agg = M @ F^T, cp.async double-buffered.
// CTA = 256 threads (8 warps, 4 o-groups x 2 bc-groups), tile 128o x 64bc.
// Epilogue RED-adds into g_agg[bc*NOUT + o] (zeroed by qc_prep).
// ---------------------------------------------------------------------------
__global__ void __launch_bounds__(256, 2) qc_gemm_mma() {
    extern __shared__ __half sm[];
    int t    = threadIdx.x;
    int wid  = t >> 5;
    int lane = t & 31;
    int bid  = blockIdx.x;
    int mt_b = bid & 7;              // o tile
    int nb   = (bid >> 3) & 1;       // bc half
    int ks   = bid >> 4;             // K split
    int o0   = mt_b * 128;
    int bc0  = nb * 64;
    int k0   = ks * KPB;
    int wo   = (wid >> 1) * 32;      // warp o offset (0/32/64/96)
    int n0w  = (wid & 1) * 32;       // warp bc offset within CTA (0/32)

    uint32_t sbase = smem_u32(sm);
    uint32_t sA[2], sB[2];
    #pragma unroll
    for (int s = 0; s < 2; s++) {
        sA[s] = sbase + (s * STAGEH) * 2;
        sB[s] = sA[s] + ATILEH * 2;
    }

    auto prefetch = [&](int stage, int kc) {
        #pragma unroll
        for (int j = 0; j < 4; j++) {
            int seg = t + j * 256;                 // 0..1023
            int row = seg >> 3, col = seg & 7;
            cp16(sA[stage] + row * 144 + col * 16,
                 &g_Mh[(o0 + row) * NIN + kc + col * 8]);
        }
        #pragma unroll
        for (int j = 0; j < 2; j++) {
            int seg = t + j * 256;                 // 0..511
            int row = seg >> 3, col = seg & 7;
            cp16(sB[stage] + row * 144 + col * 16,
                 &g_Fh[(bc0 + row) * NIN + kc + col * 8]);
        }
        cp_commit();
    };

    prefetch(0, k0);

    float acc[2][4][4];
    #pragma unroll
    for (int i = 0; i < 2; i++)
        #pragma unroll
        for (int j = 0; j < 4; j++)
            #pragma unroll
            for (int q = 0; q < 4; q++) acc[i][j][q] = 0.f;

    for (int c = 0; c < NCHUNK; c++) {
        int buf = c & 1;
        cp_wait0();
        __syncthreads();

        if (c + 1 < NCHUNK) prefetch(buf ^ 1, k0 + (c + 1) * KC);

        #pragma unroll
        for (int kk = 0; kk < KC; kk += 16) {
            uint32_t a[2][4];
            #pragma unroll
            for (int mt = 0; mt < 2; mt++)
                ldsm_x4(a[mt], sA[buf] + 2 * ((wo + mt * 16 + (lane & 15)) * ROWH
                                              + kk + (lane >> 4) * 8));
            #pragma unroll
            for (int ng = 0; ng < 2; ng++) {
                uint32_t b[4];
                ldsm_x4(b, sB[buf] + 2 * ((n0w + ng * 16 + (lane & 15)) * ROWH
                                          + kk + (lane >> 4) * 8));
                #pragma unroll
                for (int mt = 0; mt < 2; mt++) {
                    mma16816(acc[mt][ng * 2 + 0], a[mt], b[0], b[2]);
                    mma16816(acc[mt][ng * 2 + 1], a[mt], b[1], b[3]);
                }
            }
        }
    }

    // Epilogue: RED into g_agg[bc*NOUT + o].
    #pragma unroll
    for (int mt = 0; mt < 2; mt++) {
        #pragma unroll
        for (int nt = 0; nt < 4; nt++) {
            int o  = o0 + wo + mt * 16 + (lane >> 2);
            int bc = bc0 + n0w + nt * 8 + (lane & 3) * 2;
            atomicAdd(&g_agg[bc * NOUT + o],           acc[mt][nt][0]);
            atomicAdd(&g_agg[(bc + 1) * NOUT + o],     acc[mt][nt][1]);
            atomicAdd(&g_agg[bc * NOUT + o + 8],       acc[mt][nt][2]);
            atomicAdd(&g_agg[(bc + 1) * NOUT + o + 8], acc[mt][nt][3]);
        }
    }
}

// ---------------------------------------------------------------------------
// Kernel A: apply G to agg -> out.  out[b,oc,o] = sum_i G[oc,i]*agg[b*32+i][o]
// 128 blocks (4 b x 32 o-tiles of 32). All loads/stores coalesced; G work is
// over o=1024 (4x less than the old n=4096 transform).
// ---------------------------------------------------------------------------
__global__ void qc_apply(const float* __restrict__ G, float* __restrict__ out) {
    __shared__ float As[C_DIM * 33];   // agg[i][ol] 32x32 padded
    __shared__ float Gs[C_DIM * 33];   // G[oc][i]
    int t  = threadIdx.x;
    int b  = blockIdx.x >> 5;          // 0..3
    int o0 = (blockIdx.x & 31) * 32;   // o tile start

    #pragma unroll
    for (int j = 0; j < 4; j++) {
        int idx = t + j * 256;                   // 0..1023 = i*32+ol
        int i = idx >> 5, ol = idx & 31;
        As[i * 33 + ol] = g_agg[(b * 32 + i) * NOUT + o0 + ol];
        Gs[i * 33 + ol] = G[idx];                // reuse idx: oc=i, i=ol
    }
    __syncthreads();

    int ol  = t & 31;
    int ocg = t >> 5;                  // 0..7
    #pragma unroll
    for (int oo = 0; oo < 4; oo++) {
        int oc = ocg * 4 + oo;
        float s = 0.f;
        #pragma unroll
        for (int i = 0; i < 32; i++)
            s = fmaf(Gs[oc * 33 + i], As[i * 33 + ol], s);
        out[(b * 32 + oc) * NOUT + o0 + ol] = s;
    }
}

// ---------------------------------------------------------------------------
extern "C" void kernel_launch(void* const* d_in, const int* in_sizes, int n_in,
                              void* d_out, int out_size) {
    const float* features = (const float*)d_in[0];   // (4,32,4096) f32
    const float* G        = (const float*)d_in[1];   // (32,32)     f32
    const int*   idx_out  = (const int*)d_in[2];     // (E,) i32
    const int*   idx_in   = (const int*)d_in[3];     // (E,) i32
    float*       out      = (float*)d_out;           // (4,32,1024) f32
    int E = in_sizes[2];

    static bool inited = false;
    if (!inited) {
        cudaFuncSetAttribute(qc_gemm_mma,
                             cudaFuncAttributeMaxDynamicSharedMemorySize,
                             2 * STAGEH * (int)sizeof(__half));
        inited = true;
    }
    const int GEMM_SMEM = 2 * STAGEH * (int)sizeof(__half);  // 55296

    qc_prep<<<PREP_ALL / 256, 256>>>(features);
    qc_count<<<(E + 255) / 256, 256>>>(idx_out, idx_in, E);
    qc_gemm_mma<<<8 * 2 * KSPLIT, 256, GEMM_SMEM>>>();
    qc_apply<<<128, 256>>>(G, out);
}